// round 15
// baseline (speedup 1.0000x reference)
#include <cuda_runtime.h>
#include <cuda_fp16.h>
#include <cstdint>

// Problem constants (fixed: x,y in f32[4,4096,128])
#define BATCH 4
#define NPTS  4096
#define DIM   128
#define NINF_BITS 0xff800000u   // -inf (acc-max formulation)

#define ROWB   256            // bytes per row in gmem (128 fp16)
#define SSTB   272            // smem row stride bytes (68 words, 68%32==4: ldmatrix conflict-free)

#define GRID_MAIN   296       // 2 CTAs x 148 SMs, single wave
#define TOTAL_UNITS 4096      // 4 batches x 32 n-tiles x 32 m-tiles

// ---------------- global scratch (allocation-free rule) ----------------
__device__ __half  g_Ax[BATCH * NPTS * DIM];
__device__ __half  g_By[BATCH * NPTS * DIM];
__device__ float    g_x2[BATCH * NPTS];     // stores -x2/2
__device__ float    g_y2[BATCH * NPTS];     // stores -y2/2
__device__ unsigned g_rowmin[BATCH * NPTS]; // RED.MIN accumulated (clamped >=0)
__device__ unsigned g_colmin[BATCH * NPTS]; // RED.MIN accumulated (clamped >=0)
__device__ unsigned g_done;                 // completion counter (reset by hd_prep)

// ---------------- smem layout (bytes): ~103.5 KB/CTA, 2 CTAs/SM ----------------
#define A_OFF     0            // 128 * 272 = 34816
#define B0_OFF    34816
#define B1_OFF    69632
#define S_HX_OFF  104448       // 128 floats (-x2/2 for current A-tile)
#define S_HY0_OFF 104960       // 128 floats (-y2/2, tile parity 0)
#define S_HY1_OFF 105472       // 128 floats (-y2/2, tile parity 1)
#define SMEM_BYTES 105984

// ---------------- PTX helpers (sm_80+ / plain sm_100-safe) ----------------
__device__ __forceinline__ uint32_t smem_u32(const void* p) {
    uint32_t a;
    asm("{ .reg .u64 t; cvta.to.shared.u64 t, %1; cvt.u32.u64 %0, t; }" : "=r"(a) : "l"(p));
    return a;
}
__device__ __forceinline__ void cp_async16(uint32_t saddr, const void* g) {
    asm volatile("cp.async.cg.shared.global [%0], [%1], 16;" :: "r"(saddr), "l"(g));
}
#define CP_COMMIT() asm volatile("cp.async.commit_group;" ::: "memory")
#define CP_WAIT0()  asm volatile("cp.async.wait_group 0;" ::: "memory")

__device__ __forceinline__ void ldsm_x4(uint32_t* r, uint32_t addr) {
    asm volatile("ldmatrix.sync.aligned.m8n8.x4.shared.b16 {%0,%1,%2,%3}, [%4];"
                 : "=r"(r[0]), "=r"(r[1]), "=r"(r[2]), "=r"(r[3]) : "r"(addr));
}
__device__ __forceinline__ void mma_f16(float* c, const uint32_t* a, const uint32_t* b) {
    asm volatile("mma.sync.aligned.m16n8k16.row.col.f32.f16.f16.f32 "
                 "{%0,%1,%2,%3}, {%4,%5,%6,%7}, {%8,%9}, {%0,%1,%2,%3};"
                 : "+f"(c[0]), "+f"(c[1]), "+f"(c[2]), "+f"(c[3])
                 : "r"(a[0]), "r"(a[1]), "r"(a[2]), "r"(a[3]), "r"(b[0]), "r"(b[1]));
}

// ---------------------------------------------------------------------------
// Kernel 1: fp16 convert + (-0.5 * squared norm) + min-array + counter init.
// Quarter-warp (8 lanes) per row: 4 consecutive LDG.128 per thread (MLP=4).
// ---------------------------------------------------------------------------
__global__ void hd_prep(const float* __restrict__ x, const float* __restrict__ y) {
    int gtid = blockIdx.x * blockDim.x + threadIdx.x;
    if (gtid < BATCH * NPTS) {
        g_colmin[gtid] = 0x7f800000u;   // +inf
        g_rowmin[gtid] = 0x7f800000u;
    }
    if (gtid == 0) g_done = 0;

    int qw   = gtid >> 3;
    int hl   = gtid & 7;
    bool isx = qw < BATCH * NPTS;
    int row  = isx ? qw : qw - BATCH * NPTS;
    const float* src = (isx ? x : y) + (size_t)row * DIM;

    float4 v0 = ((const float4*)src)[4 * hl];
    float4 v1 = ((const float4*)src)[4 * hl + 1];
    float4 v2 = ((const float4*)src)[4 * hl + 2];
    float4 v3 = ((const float4*)src)[4 * hl + 3];

    __half2 c0 = __floats2half2_rn(v0.x, v0.y), c1 = __floats2half2_rn(v0.z, v0.w);
    __half2 c2 = __floats2half2_rn(v1.x, v1.y), c3 = __floats2half2_rn(v1.z, v1.w);
    __half2 c4 = __floats2half2_rn(v2.x, v2.y), c5 = __floats2half2_rn(v2.z, v2.w);
    __half2 c6 = __floats2half2_rn(v3.x, v3.y), c7 = __floats2half2_rn(v3.z, v3.w);
    uint4 p0, p1;
    p0.x = *(unsigned*)&c0; p0.y = *(unsigned*)&c1;
    p0.z = *(unsigned*)&c2; p0.w = *(unsigned*)&c3;
    p1.x = *(unsigned*)&c4; p1.y = *(unsigned*)&c5;
    p1.z = *(unsigned*)&c6; p1.w = *(unsigned*)&c7;

    __half* dst = (isx ? g_Ax : g_By) + (size_t)row * DIM;
    ((uint4*)dst)[2 * hl]     = p0;
    ((uint4*)dst)[2 * hl + 1] = p1;

    float s = v0.x * v0.x + v0.y * v0.y + v0.z * v0.z + v0.w * v0.w
            + v1.x * v1.x + v1.y * v1.y + v1.z * v1.z + v1.w * v1.w
            + v2.x * v2.x + v2.y * v2.y + v2.z * v2.z + v2.w * v2.w
            + v3.x * v3.x + v3.y * v3.y + v3.z * v3.z + v3.w * v3.w;
    #pragma unroll
    for (int o = 4; o > 0; o >>= 1) s += __shfl_xor_sync(0xffffffffu, s, o);
    if (hl == 0) {
        float h = -0.5f * s;
        if (isx) g_x2[row] = h;
        else     g_y2[row] = h;
    }
}

// ---------------------------------------------------------------------------
// Kernel 2: fp16 mma.sync GEMM, occ 2, balanced persistent ranges, with the
// inter-tile serial path pulled into the mainloop:
//  * colmin flush of tile t-1 is DEFERRED: its 8 per-thread maxima (pcm)
//    retire one per k-step of tile t's mainloop (shfl+RED hidden under HMMA);
//    pcm starts at -inf -> first flush writes +inf -> atomicMin no-op.
//  * hy (-y2/2) staged to smem by cp.async double buffer (no init-path LDG).
//  * A fragments wrap around (ks=7 preloads ks=0; A is tile-invariant),
//    re-primed only at A-tile boundaries.
// acc preloaded with -(x2+y2)/2 so min(d2) == max(acc); epilogue 2 FMAX/elem.
// ---------------------------------------------------------------------------
extern __shared__ unsigned char smem_raw[];

__global__ __launch_bounds__(256, 2)
void hd_main(float* __restrict__ out) {
    unsigned char* sm = smem_raw;
    const uint32_t sbase = smem_u32(sm);
    const int tid  = threadIdx.x;
    const int wid  = tid >> 5;
    const int ln   = tid & 31;
    const int wm   = wid >> 2;       // 0..1  (M half: 64 rows)
    const int wn   = wid & 3;        // 0..3  (N quarter: 32 cols)

    const int prow = tid >> 4;          // base row for fills
    const int pcol = tid & 15;          // 16B chunk within row

    const int lo = (blockIdx.x * TOTAL_UNITS) / GRID_MAIN;
    const int hi = ((blockIdx.x + 1) * TOTAL_UNITS) / GRID_MAIN;

    float* s_hx = (float*)(sm + S_HX_OFF);

    // ldmatrix base addresses
    uint32_t aaddr[4], baddr[2];
    #pragma unroll
    for (int mi = 0; mi < 4; mi++)
        aaddr[mi] = sbase + A_OFF + (wm * 64 + mi * 16 + (ln & 15)) * SSTB + (ln >> 4) * 16;
    #pragma unroll
    for (int pr = 0; pr < 2; pr++)
        baddr[pr] = sbase + B0_OFF +
                    (wn * 32 + pr * 16 + ((ln >> 4) & 1) * 8 + (ln & 7)) * SSTB +
                    ((ln >> 3) & 1) * 16;

    // ---- prologue: B fill + hy stage for unit lo ----
    {
        int b0 = lo >> 10, t0 = lo & 31;
        const unsigned char* bsrc =
            (const unsigned char*)(g_By + (size_t)(b0 * NPTS + t0 * 128) * DIM);
        uint32_t boff = sbase + ((lo & 1) ? B1_OFF : B0_OFF);
        #pragma unroll
        for (int it = 0; it < 8; it++) {
            int row = prow + it * 16;
            cp_async16(boff + row * SSTB + pcol * 16, bsrc + (size_t)row * ROWB + pcol * 16);
        }
        if (tid < 32)
            cp_async16(sbase + ((lo & 1) ? S_HY1_OFF : S_HY0_OFF) + tid * 16,
                       (const unsigned char*)(g_y2 + b0 * NPTS + t0 * 128) + tid * 16);
        CP_COMMIT();
    }

    int cur_ant = -1, cur_base = 0;     // current A-tile id; gmem row base b*NPTS+n0
    float rm[8];                         // rowmin acc-max for current A-tile
    float pcm[8];                        // deferred colmin maxima of previous tile
    int   pbase = 0;                     // colmin base of previous tile
    #pragma unroll
    for (int r = 0; r < 8; r++) { rm[r] = __uint_as_float(NINF_BITS); pcm[r] = __uint_as_float(NINF_BITS); }

    uint32_t afr[2][4][4];               // A-fragment pipeline (persistent)

    for (int u = lo; u < hi; u++) {
        const int b = u >> 10, t = u & 31, ant = u >> 5;
        const int n0 = (ant & 31) * 128;

        if (ant != cur_ant) {
            // flush partial rowmin for the previous A-tile
            if (cur_ant >= 0) {
                #pragma unroll
                for (int r = 0; r < 8; r++) {
                    float v = rm[r];
                    v = fmaxf(v, __shfl_xor_sync(0xffffffffu, v, 1));
                    v = fmaxf(v, __shfl_xor_sync(0xffffffffu, v, 2));
                    if ((ln & 3) == 0) {
                        int row = wm * 64 + (r >> 1) * 16 + (ln >> 2) + (r & 1) * 8;
                        float d2 = fmaxf(-2.0f * v, 0.0f);
                        atomicMin(&g_rowmin[cur_base + row], __float_as_uint(d2));
                    }
                    rm[r] = __uint_as_float(NINF_BITS);
                }
            }
            // load A tile + hx (prior unit's barrier guarantees A smem is free)
            cur_base = b * NPTS + n0;
            const unsigned char* asrc = (const unsigned char*)(g_Ax + (size_t)cur_base * DIM);
            #pragma unroll
            for (int it = 0; it < 8; it++) {
                int row = prow + it * 16;
                cp_async16(sbase + A_OFF + row * SSTB + pcol * 16,
                           asrc + (size_t)row * ROWB + pcol * 16);
            }
            CP_COMMIT();
            if (tid < 128) s_hx[tid] = g_x2[cur_base + tid];
            CP_WAIT0();            // A landed (and this unit's B + hy, issued earlier)
            __syncthreads();
            cur_ant = ant;
            // prime the A-fragment pipeline (ks=0)
            #pragma unroll
            for (int mi = 0; mi < 4; mi++) ldsm_x4(afr[0][mi], aaddr[mi]);
        }

        const uint32_t bsel = (u & 1) ? (B1_OFF - B0_OFF) : 0u;
        const bool pf = (u + 1 < hi);
        const int u1 = pf ? (u + 1) : u;
        const int b1 = u1 >> 10, t1 = u1 & 31;
        const unsigned char* nbsrc =
            (const unsigned char*)(g_By + (size_t)(b1 * NPTS + t1 * 128) * DIM);
        const uint32_t nboff = sbase + ((u1 & 1) ? B1_OFF : B0_OFF);
        const float* s_hy = (const float*)(sm + ((u & 1) ? S_HY1_OFF : S_HY0_OFF));

        // acc preload: -(x2+y2)/2 from smem (short-lived temps)
        float acc[4][4][4];
        {
            float hxv[4][2], hyv[4][2];
            #pragma unroll
            for (int mi = 0; mi < 4; mi++)
                #pragma unroll
                for (int k2 = 0; k2 < 2; k2++)
                    hxv[mi][k2] = s_hx[wm * 64 + mi * 16 + (ln >> 2) + k2 * 8];
            #pragma unroll
            for (int ni = 0; ni < 4; ni++)
                #pragma unroll
                for (int e = 0; e < 2; e++)
                    hyv[ni][e] = s_hy[wn * 32 + ni * 8 + (ln & 3) * 2 + e];
            #pragma unroll
            for (int mi = 0; mi < 4; mi++)
                #pragma unroll
                for (int ni = 0; ni < 4; ni++)
                    #pragma unroll
                    for (int k = 0; k < 4; k++)
                        acc[mi][ni][k] = hxv[mi][k >> 1] + hyv[ni][k & 1];
        }

        // B fragment pipeline: preload ks=0
        uint32_t bq[2][2][4];
        #pragma unroll
        for (int pr = 0; pr < 2; pr++) ldsm_x4(bq[0][pr], baddr[pr] + bsel);

        // ---- mainloop: K=128 in 8 k-steps. Each ks also retires one deferred
        //      colmin flush (3 SHFL + RED) and issues B/hy gmem prefetches. ----
        #pragma unroll
        for (int ks = 0; ks < 8; ks++) {
            if (pf) {   // 1 gmem->smem B prefetch chunk per thread per ks
                int row = prow + ks * 16;
                cp_async16(nboff + row * SSTB + pcol * 16,
                           nbsrc + (size_t)row * ROWB + pcol * 16);
                if (ks == 0 && tid < 32)   // hy stage for next unit
                    cp_async16(sbase + ((u1 & 1) ? S_HY1_OFF : S_HY0_OFF) + tid * 16,
                               (const unsigned char*)(g_y2 + b1 * NPTS + t1 * 128) + tid * 16);
            }
            // next-step fragments: B for ks+1 (ks<7); A wraps (ks=7 -> ks0, same tile data)
            {
                const int nks = (ks + 1) & 7;
                #pragma unroll
                for (int mi = 0; mi < 4; mi++)
                    ldsm_x4(afr[nks & 1][mi], aaddr[mi] + nks * 32);
                if (ks < 7) {
                    #pragma unroll
                    for (int pr = 0; pr < 2; pr++)
                        ldsm_x4(bq[(ks + 1) & 1][pr], baddr[pr] + bsel + (ks + 1) * 32);
                }
            }
            // deferred colmin flush: pair (ni = ks>>1, e = ks&1) of previous tile
            {
                float v = pcm[ks];
                v = fmaxf(v, __shfl_xor_sync(0xffffffffu, v, 4));
                v = fmaxf(v, __shfl_xor_sync(0xffffffffu, v, 8));
                v = fmaxf(v, __shfl_xor_sync(0xffffffffu, v, 16));
                if (ln < 4) {
                    float d2 = fmaxf(-2.0f * v, 0.0f);
                    atomicMin(&g_colmin[pbase + wn * 32 + (ks >> 1) * 8 + ln * 2 + (ks & 1)],
                              __float_as_uint(d2));
                }
            }
            #pragma unroll
            for (int mi = 0; mi < 4; mi++)
                #pragma unroll
                for (int ni = 0; ni < 4; ni++)
                    mma_f16(acc[mi][ni], afr[ks & 1][mi], &bq[ks & 1][ni >> 1][(ni & 1) * 2]);
        }
        if (pf) CP_COMMIT();

        // ---- epilogue: 2 FMAX per element; cmv goes straight into pcm ----
        #pragma unroll
        for (int r = 0; r < 8; r++) pcm[r] = __uint_as_float(NINF_BITS);
        #pragma unroll
        for (int mi = 0; mi < 4; mi++)
            #pragma unroll
            for (int ni = 0; ni < 4; ni++)
                #pragma unroll
                for (int k = 0; k < 4; k++) {
                    float a = acc[mi][ni][k];
                    rm[mi * 2 + (k >> 1)] = fmaxf(rm[mi * 2 + (k >> 1)], a);
                    pcm[ni * 2 + (k & 1)] = fmaxf(pcm[ni * 2 + (k & 1)], a);
                }
        pbase = b * NPTS + t * 128;

        if (pf) CP_WAIT0();   // this thread's prefetch chunks landed
        __syncthreads();      // everyone done reading old buffers before overwrite
    }

    // ---- drain: last tile's colmin + last A-tile's rowmin ----
    #pragma unroll
    for (int ks = 0; ks < 8; ks++) {
        float v = pcm[ks];
        v = fmaxf(v, __shfl_xor_sync(0xffffffffu, v, 4));
        v = fmaxf(v, __shfl_xor_sync(0xffffffffu, v, 8));
        v = fmaxf(v, __shfl_xor_sync(0xffffffffu, v, 16));
        if (ln < 4) {
            float d2 = fmaxf(-2.0f * v, 0.0f);
            atomicMin(&g_colmin[pbase + wn * 32 + (ks >> 1) * 8 + ln * 2 + (ks & 1)],
                      __float_as_uint(d2));
        }
    }
    #pragma unroll
    for (int r = 0; r < 8; r++) {
        float v = rm[r];
        v = fmaxf(v, __shfl_xor_sync(0xffffffffu, v, 1));
        v = fmaxf(v, __shfl_xor_sync(0xffffffffu, v, 2));
        if ((ln & 3) == 0) {
            int row = wm * 64 + (r >> 1) * 16 + (ln >> 2) + (r & 1) * 8;
            float d2 = fmaxf(-2.0f * v, 0.0f);
            atomicMin(&g_rowmin[cur_base + row], __float_as_uint(d2));
        }
    }

    // ---- fused finalize: last CTA reduces everything ----
    __threadfence();                       // make our REDs visible
    __shared__ unsigned s_last;
    if (tid == 0) s_last = (atomicAdd(&g_done, 1u) == GRID_MAIN - 1u) ? 1u : 0u;
    __syncthreads();
    if (s_last) {
        float* s_red = (float*)(sm + B0_OFF);   // reuse smem
        float sum = 0.0f;
        for (int bb = 0; bb < BATCH; bb++) {
            float mx = 0.0f;
            for (int i = tid; i < NPTS; i += 256) {
                mx = fmaxf(mx, __uint_as_float(g_rowmin[bb * NPTS + i]));
                mx = fmaxf(mx, __uint_as_float(g_colmin[bb * NPTS + i]));
            }
            s_red[tid] = mx;
            __syncthreads();
            for (int st = 128; st > 0; st >>= 1) {
                if (tid < st) s_red[tid] = fmaxf(s_red[tid], s_red[tid + st]);
                __syncthreads();
            }
            if (tid == 0) sum += sqrtf(s_red[0]);
            __syncthreads();
        }
        if (tid == 0) out[0] = sum * (1.0f / BATCH);
    }
}

// ---------------------------------------------------------------------------
extern "C" void kernel_launch(void* const* d_in, const int* in_sizes, int n_in,
                              void* d_out, int out_size) {
    const float* x = (const float*)d_in[0];
    const float* y = (const float*)d_in[1];
    float* out = (float*)d_out;

    (void)cudaFuncSetAttribute(hd_main, cudaFuncAttributeMaxDynamicSharedMemorySize,
                               SMEM_BYTES);

    hd_prep<<<1024, 256>>>(x, y);
    hd_main<<<GRID_MAIN, 256, SMEM_BYTES>>>(out);
}

// round 16
// speedup vs baseline: 1.1759x; 1.1759x over previous
#include <cuda_runtime.h>
#include <cuda_fp16.h>
#include <cstdint>

// Problem constants (fixed: x,y in f32[4,4096,128])
#define BATCH 4
#define NPTS  4096
#define DIM   128
#define NINF_BITS 0xff800000u   // -inf (acc-max formulation)

#define ROWB   256            // bytes per row in gmem (128 fp16)
#define SSTB   272            // smem row stride bytes (68 words, 68%32==4: ldmatrix conflict-free)

#define GRID_MAIN   296       // 2 CTAs x 148 SMs, single wave
#define TOTAL_UNITS 4096      // 4 batches x 32 n-tiles x 32 m-tiles

// ---------------- global scratch (allocation-free rule) ----------------
__device__ __half  g_Ax[BATCH * NPTS * DIM];
__device__ __half  g_By[BATCH * NPTS * DIM];
__device__ float    g_x2[BATCH * NPTS];     // stores -x2/2
__device__ float    g_y2[BATCH * NPTS];     // stores -y2/2
__device__ unsigned g_rowmin[BATCH * NPTS]; // RED.MIN accumulated (clamped >=0)
__device__ unsigned g_colmin[BATCH * NPTS]; // RED.MIN accumulated (clamped >=0)
__device__ unsigned g_done;                 // completion counter (reset by hd_prep)

// ---------------- smem layout (bytes): ~102.5 KB/CTA, 2 CTAs/SM ----------------
#define A_OFF     0            // 128 * 272 = 34816
#define B0_OFF    34816
#define B1_OFF    69632
#define S_HX_OFF  104448       // 128 floats (-x2/2 for current A-tile)
#define SMEM_BYTES 104960

// ---------------- PTX helpers (sm_80+ / plain sm_100-safe) ----------------
__device__ __forceinline__ uint32_t smem_u32(const void* p) {
    uint32_t a;
    asm("{ .reg .u64 t; cvta.to.shared.u64 t, %1; cvt.u32.u64 %0, t; }" : "=r"(a) : "l"(p));
    return a;
}
__device__ __forceinline__ void cp_async16(uint32_t saddr, const void* g) {
    asm volatile("cp.async.cg.shared.global [%0], [%1], 16;" :: "r"(saddr), "l"(g));
}
#define CP_COMMIT() asm volatile("cp.async.commit_group;" ::: "memory")
#define CP_WAIT0()  asm volatile("cp.async.wait_group 0;" ::: "memory")

__device__ __forceinline__ void ldsm_x4(uint32_t* r, uint32_t addr) {
    asm volatile("ldmatrix.sync.aligned.m8n8.x4.shared.b16 {%0,%1,%2,%3}, [%4];"
                 : "=r"(r[0]), "=r"(r[1]), "=r"(r[2]), "=r"(r[3]) : "r"(addr));
}
__device__ __forceinline__ void mma_f16(float* c, const uint32_t* a, const uint32_t* b) {
    asm volatile("mma.sync.aligned.m16n8k16.row.col.f32.f16.f16.f32 "
                 "{%0,%1,%2,%3}, {%4,%5,%6,%7}, {%8,%9}, {%0,%1,%2,%3};"
                 : "+f"(c[0]), "+f"(c[1]), "+f"(c[2]), "+f"(c[3])
                 : "r"(a[0]), "r"(a[1]), "r"(a[2]), "r"(a[3]), "r"(b[0]), "r"(b[1]));
}

// ---------------------------------------------------------------------------
// Kernel 1: fp16 convert + (-0.5 * squared norm) + min-array + counter init.
// Quarter-warp (8 lanes) per row: 4 consecutive LDG.128 per thread (MLP=4).
// ---------------------------------------------------------------------------
__global__ void hd_prep(const float* __restrict__ x, const float* __restrict__ y) {
    int gtid = blockIdx.x * blockDim.x + threadIdx.x;
    if (gtid < BATCH * NPTS) {
        g_colmin[gtid] = 0x7f800000u;   // +inf
        g_rowmin[gtid] = 0x7f800000u;
    }
    if (gtid == 0) g_done = 0;

    int qw   = gtid >> 3;
    int hl   = gtid & 7;
    bool isx = qw < BATCH * NPTS;
    int row  = isx ? qw : qw - BATCH * NPTS;
    const float* src = (isx ? x : y) + (size_t)row * DIM;

    float4 v0 = ((const float4*)src)[4 * hl];
    float4 v1 = ((const float4*)src)[4 * hl + 1];
    float4 v2 = ((const float4*)src)[4 * hl + 2];
    float4 v3 = ((const float4*)src)[4 * hl + 3];

    __half2 c0 = __floats2half2_rn(v0.x, v0.y), c1 = __floats2half2_rn(v0.z, v0.w);
    __half2 c2 = __floats2half2_rn(v1.x, v1.y), c3 = __floats2half2_rn(v1.z, v1.w);
    __half2 c4 = __floats2half2_rn(v2.x, v2.y), c5 = __floats2half2_rn(v2.z, v2.w);
    __half2 c6 = __floats2half2_rn(v3.x, v3.y), c7 = __floats2half2_rn(v3.z, v3.w);
    uint4 p0, p1;
    p0.x = *(unsigned*)&c0; p0.y = *(unsigned*)&c1;
    p0.z = *(unsigned*)&c2; p0.w = *(unsigned*)&c3;
    p1.x = *(unsigned*)&c4; p1.y = *(unsigned*)&c5;
    p1.z = *(unsigned*)&c6; p1.w = *(unsigned*)&c7;

    __half* dst = (isx ? g_Ax : g_By) + (size_t)row * DIM;
    ((uint4*)dst)[2 * hl]     = p0;
    ((uint4*)dst)[2 * hl + 1] = p1;

    float s = v0.x * v0.x + v0.y * v0.y + v0.z * v0.z + v0.w * v0.w
            + v1.x * v1.x + v1.y * v1.y + v1.z * v1.z + v1.w * v1.w
            + v2.x * v2.x + v2.y * v2.y + v2.z * v2.z + v2.w * v2.w
            + v3.x * v3.x + v3.y * v3.y + v3.z * v3.z + v3.w * v3.w;
    #pragma unroll
    for (int o = 4; o > 0; o >>= 1) s += __shfl_xor_sync(0xffffffffu, s, o);
    if (hl == 0) {
        float h = -0.5f * s;
        if (isx) g_x2[row] = h;
        else     g_y2[row] = h;
    }
}

// ---------------------------------------------------------------------------
// Kernel 2: fp16 mma.sync GEMM, occ 2, balanced persistent ranges (R14 base,
// 71.8us) with two placement-only changes:
//  * A-fragment wraparound: ks=7 preloads afr ks=0 (A is tile-invariant);
//    the 4-LDSM prime leaves the serial tile-start, re-primed only at
//    A-tile boundaries.
//  * B gmem prefetch front-loaded: 2 chunks/thread per k-step over ks 0..3,
//    so the last chunk has >=4 k-steps to land before CP_WAIT0.
// acc preloaded with -(x2+y2)/2 so min(d2) == max(acc); epilogue 2 FMAX/elem;
// colmin flush post-barrier (proven placement). Fused last-CTA finalize.
// ---------------------------------------------------------------------------
extern __shared__ unsigned char smem_raw[];

__global__ __launch_bounds__(256, 2)
void hd_main(float* __restrict__ out) {
    unsigned char* sm = smem_raw;
    const uint32_t sbase = smem_u32(sm);
    const int tid  = threadIdx.x;
    const int wid  = tid >> 5;
    const int ln   = tid & 31;
    const int wm   = wid >> 2;       // 0..1  (M half: 64 rows)
    const int wn   = wid & 3;        // 0..3  (N quarter: 32 cols)

    const int prow = tid >> 4;          // base row for fills
    const int pcol = tid & 15;          // 16B chunk within row

    const int lo = (blockIdx.x * TOTAL_UNITS) / GRID_MAIN;
    const int hi = ((blockIdx.x + 1) * TOTAL_UNITS) / GRID_MAIN;

    float* s_hx = (float*)(sm + S_HX_OFF);

    // ldmatrix base addresses
    uint32_t aaddr[4], baddr[2];
    #pragma unroll
    for (int mi = 0; mi < 4; mi++)
        aaddr[mi] = sbase + A_OFF + (wm * 64 + mi * 16 + (ln & 15)) * SSTB + (ln >> 4) * 16;
    #pragma unroll
    for (int pr = 0; pr < 2; pr++)
        baddr[pr] = sbase + B0_OFF +
                    (wn * 32 + pr * 16 + ((ln >> 4) & 1) * 8 + (ln & 7)) * SSTB +
                    ((ln >> 3) & 1) * 16;

    // ---- prologue: B fill for unit lo; hy for unit lo ----
    {
        int b0 = lo >> 10, t0 = lo & 31;
        const unsigned char* bsrc =
            (const unsigned char*)(g_By + (size_t)(b0 * NPTS + t0 * 128) * DIM);
        uint32_t boff = sbase + ((lo & 1) ? B1_OFF : B0_OFF);
        #pragma unroll
        for (int it = 0; it < 8; it++) {
            int row = prow + it * 16;
            cp_async16(boff + row * SSTB + pcol * 16, bsrc + (size_t)row * ROWB + pcol * 16);
        }
        CP_COMMIT();
    }
    float hy[4][2];
    {
        int b0 = lo >> 10, t0 = lo & 31;
        #pragma unroll
        for (int ni = 0; ni < 4; ni++)
            #pragma unroll
            for (int e = 0; e < 2; e++)
                hy[ni][e] = g_y2[b0 * NPTS + t0 * 128 + wn * 32 + ni * 8 + (ln & 3) * 2 + e];
    }

    int cur_ant = -1, cur_base = 0;     // current A-tile id; gmem row base b*NPTS+n0
    float rm[8];
    #pragma unroll
    for (int r = 0; r < 8; r++) rm[r] = __uint_as_float(NINF_BITS);

    uint32_t afr[2][4][4];               // A-fragment pipeline (persistent per A-tile)

    for (int u = lo; u < hi; u++) {
        const int b = u >> 10, t = u & 31, ant = u >> 5;
        const int n0 = (ant & 31) * 128;

        if (ant != cur_ant) {
            // flush partial rowmin for the previous A-tile
            if (cur_ant >= 0) {
                #pragma unroll
                for (int r = 0; r < 8; r++) {
                    float v = rm[r];
                    v = fmaxf(v, __shfl_xor_sync(0xffffffffu, v, 1));
                    v = fmaxf(v, __shfl_xor_sync(0xffffffffu, v, 2));
                    if ((ln & 3) == 0) {
                        int row = wm * 64 + (r >> 1) * 16 + (ln >> 2) + (r & 1) * 8;
                        float d2 = fmaxf(-2.0f * v, 0.0f);
                        atomicMin(&g_rowmin[cur_base + row], __float_as_uint(d2));
                    }
                    rm[r] = __uint_as_float(NINF_BITS);
                }
            }
            // load A tile + hx (prior unit's barrier guarantees A smem is free)
            cur_base = b * NPTS + n0;
            const unsigned char* asrc = (const unsigned char*)(g_Ax + (size_t)cur_base * DIM);
            #pragma unroll
            for (int it = 0; it < 8; it++) {
                int row = prow + it * 16;
                cp_async16(sbase + A_OFF + row * SSTB + pcol * 16,
                           asrc + (size_t)row * ROWB + pcol * 16);
            }
            CP_COMMIT();
            if (tid < 128) s_hx[tid] = g_x2[cur_base + tid];
            CP_WAIT0();            // A landed (and this unit's B, issued earlier)
            __syncthreads();
            cur_ant = ant;
            // prime the A-fragment pipeline (ks=0)
            #pragma unroll
            for (int mi = 0; mi < 4; mi++) ldsm_x4(afr[0][mi], aaddr[mi]);
        }

        const uint32_t bsel = (u & 1) ? (B1_OFF - B0_OFF) : 0u;
        const bool pf = (u + 1 < hi);
        const int u1 = pf ? (u + 1) : u;
        const int b1 = u1 >> 10, t1 = u1 & 31;
        const unsigned char* nbsrc =
            (const unsigned char*)(g_By + (size_t)(b1 * NPTS + t1 * 128) * DIM);
        const uint32_t nboff = sbase + ((u1 & 1) ? B1_OFF : B0_OFF);

        // acc preload: -(x2+y2)/2
        float acc[4][4][4];
        {
            float hxv[4][2];
            #pragma unroll
            for (int mi = 0; mi < 4; mi++)
                #pragma unroll
                for (int k2 = 0; k2 < 2; k2++)
                    hxv[mi][k2] = s_hx[wm * 64 + mi * 16 + (ln >> 2) + k2 * 8];
            #pragma unroll
            for (int mi = 0; mi < 4; mi++)
                #pragma unroll
                for (int ni = 0; ni < 4; ni++)
                    #pragma unroll
                    for (int k = 0; k < 4; k++)
                        acc[mi][ni][k] = hxv[mi][k >> 1] + hy[ni][k & 1];
        }

        // prefetch hy for next unit (lands during this unit's mainloop)
        #pragma unroll
        for (int ni = 0; ni < 4; ni++)
            #pragma unroll
            for (int e = 0; e < 2; e++)
                hy[ni][e] = g_y2[b1 * NPTS + t1 * 128 + wn * 32 + ni * 8 + (ln & 3) * 2 + e];

        // B fragment pipeline: preload ks=0
        uint32_t bq[2][2][4];
        #pragma unroll
        for (int pr = 0; pr < 2; pr++) ldsm_x4(bq[0][pr], baddr[pr] + bsel);

        // ---- mainloop: K=128 in 8 k-steps. B gmem prefetch front-loaded
        //      (2 chunks/thread, ks 0..3); A frags wrap (ks=7 loads ks=0). ----
        #pragma unroll
        for (int ks = 0; ks < 8; ks++) {
            if (pf && ks < 4) {
                int row0 = prow + ks * 32;
                cp_async16(nboff + row0 * SSTB + pcol * 16,
                           nbsrc + (size_t)row0 * ROWB + pcol * 16);
                int row1 = row0 + 16;
                cp_async16(nboff + row1 * SSTB + pcol * 16,
                           nbsrc + (size_t)row1 * ROWB + pcol * 16);
            }
            {
                const int nks = (ks + 1) & 7;
                #pragma unroll
                for (int mi = 0; mi < 4; mi++)
                    ldsm_x4(afr[nks & 1][mi], aaddr[mi] + nks * 32);
                if (ks < 7) {
                    #pragma unroll
                    for (int pr = 0; pr < 2; pr++)
                        ldsm_x4(bq[(ks + 1) & 1][pr], baddr[pr] + bsel + (ks + 1) * 32);
                }
            }
            #pragma unroll
            for (int mi = 0; mi < 4; mi++)
                #pragma unroll
                for (int ni = 0; ni < 4; ni++)
                    mma_f16(acc[mi][ni], afr[ks & 1][mi], &bq[ks & 1][ni >> 1][(ni & 1) * 2]);
        }
        if (pf) CP_COMMIT();

        // ---- epilogue: 2 FMAX per element ----
        float cmv[4][2];
        #pragma unroll
        for (int ni = 0; ni < 4; ni++)
            #pragma unroll
            for (int e = 0; e < 2; e++) cmv[ni][e] = __uint_as_float(NINF_BITS);

        #pragma unroll
        for (int mi = 0; mi < 4; mi++)
            #pragma unroll
            for (int ni = 0; ni < 4; ni++)
                #pragma unroll
                for (int k = 0; k < 4; k++) {
                    float a = acc[mi][ni][k];
                    rm[mi * 2 + (k >> 1)] = fmaxf(rm[mi * 2 + (k >> 1)], a);
                    cmv[ni][k & 1]        = fmaxf(cmv[ni][k & 1], a);
                }

        if (pf) CP_WAIT0();   // this thread's B prefetch chunks landed
        __syncthreads();      // everyone done reading old buffer before overwrite

        // colmin flush AFTER the barrier: shfl-max + fire-and-forget RED.MIN
        #pragma unroll
        for (int ni = 0; ni < 4; ni++)
            #pragma unroll
            for (int e = 0; e < 2; e++) {
                float v = cmv[ni][e];
                v = fmaxf(v, __shfl_xor_sync(0xffffffffu, v, 4));
                v = fmaxf(v, __shfl_xor_sync(0xffffffffu, v, 8));
                v = fmaxf(v, __shfl_xor_sync(0xffffffffu, v, 16));
                if (ln < 4) {
                    float d2 = fmaxf(-2.0f * v, 0.0f);
                    atomicMin(&g_colmin[b * NPTS + t * 128 + wn * 32 + ni * 8 + ln * 2 + e],
                              __float_as_uint(d2));
                }
            }
    }

    // ---- final rowmin flush for the last A-tile ----
    #pragma unroll
    for (int r = 0; r < 8; r++) {
        float v = rm[r];
        v = fmaxf(v, __shfl_xor_sync(0xffffffffu, v, 1));
        v = fmaxf(v, __shfl_xor_sync(0xffffffffu, v, 2));
        if ((ln & 3) == 0) {
            int row = wm * 64 + (r >> 1) * 16 + (ln >> 2) + (r & 1) * 8;
            float d2 = fmaxf(-2.0f * v, 0.0f);
            atomicMin(&g_rowmin[cur_base + row], __float_as_uint(d2));
        }
    }

    // ---- fused finalize: last CTA reduces everything ----
    __threadfence();                       // make our REDs visible
    __shared__ unsigned s_last;
    if (tid == 0) s_last = (atomicAdd(&g_done, 1u) == GRID_MAIN - 1u) ? 1u : 0u;
    __syncthreads();
    if (s_last) {
        float* s_red = (float*)(sm + B0_OFF);   // reuse smem
        float sum = 0.0f;
        for (int bb = 0; bb < BATCH; bb++) {
            float mx = 0.0f;
            for (int i = tid; i < NPTS; i += 256) {
                mx = fmaxf(mx, __uint_as_float(g_rowmin[bb * NPTS + i]));
                mx = fmaxf(mx, __uint_as_float(g_colmin[bb * NPTS + i]));
            }
            s_red[tid] = mx;
            __syncthreads();
            for (int st = 128; st > 0; st >>= 1) {
                if (tid < st) s_red[tid] = fmaxf(s_red[tid], s_red[tid + st]);
                __syncthreads();
            }
            if (tid == 0) sum += sqrtf(s_red[0]);
            __syncthreads();
        }
        if (tid == 0) out[0] = sum * (1.0f / BATCH);
    }
}

// ---------------------------------------------------------------------------
extern "C" void kernel_launch(void* const* d_in, const int* in_sizes, int n_in,
                              void* d_out, int out_size) {
    const float* x = (const float*)d_in[0];
    const float* y = (const float*)d_in[1];
    float* out = (float*)d_out;

    (void)cudaFuncSetAttribute(hd_main, cudaFuncAttributeMaxDynamicSharedMemorySize,
                               SMEM_BYTES);

    hd_prep<<<1024, 256>>>(x, y);
    hd_main<<<GRID_MAIN, 256, SMEM_BYTES>>>(out);
}